// round 8
// baseline (speedup 1.0000x reference)
#include <cuda_runtime.h>

#define NQ      16
#define DSTATE  (1 << NQ)      // 65536
#define BATCH   64
#define NLAYERS 4
#define PPL     93
#define NPAIR   15
#define NSTATE  (BATCH * DSTATE)
#define MASKN   (NSTATE - 1)

// XOR swizzle on u64 tile index: conflict-free for all stage access patterns
#define SW(i) (((i) ^ (((i) >> 5) & 31)) & 4095)

typedef unsigned long long u64;

// scratch state (32 MB) + dual-packed fused gate matrices
__device__ u64 g_state[NSTATE];
__device__ u64 g_gates2[NLAYERS][NPAIR][32];   // [0..15]=(re,re) packed, [16..31]=(im,-im) packed

// ---------- packed f32x2 helpers ----------
__device__ __forceinline__ u64 pack2(float x, float y) {
    u64 r; asm("mov.b64 %0, {%1, %2};" : "=l"(r) : "f"(x), "f"(y)); return r;
}
__device__ __forceinline__ u64 ffma2(u64 a, u64 b, u64 c) {
    u64 r; asm("fma.rn.f32x2 %0, %1, %2, %3;" : "=l"(r) : "l"(a), "l"(b), "l"(c)); return r;
}
__device__ __forceinline__ u64 fmul2(u64 a, u64 b) {
    u64 r; asm("mul.rn.f32x2 %0, %1, %2;" : "=l"(r) : "l"(a), "l"(b)); return r;
}
__device__ __forceinline__ u64 fadd2(u64 a, u64 b) {
    u64 r; asm("add.rn.f32x2 %0, %1, %2;" : "=l"(r) : "l"(a), "l"(b)); return r;
}
__device__ __forceinline__ u64 swap2(u64 v) {
    u64 r;
    asm("{ .reg .b32 lo, hi; mov.b64 {lo, hi}, %1; mov.b64 %0, {hi, lo}; }" : "=l"(r) : "l"(v));
    return r;
}

// ---------- gate preparation (scalar complex, trivial cost) ----------
__device__ __forceinline__ float2 cmulc(float2 a, float2 b) {
    return make_float2(a.x * b.x - a.y * b.y, a.x * b.y + a.y * b.x);
}
__device__ __forceinline__ float2 cfmac(float2 a, float2 b, float2 c) {
    c.x = fmaf(a.x, b.x, fmaf(-a.y, b.y, c.x));
    c.y = fmaf(a.x, b.y, fmaf(a.y, b.x, c.y));
    return c;
}
__device__ void mat4mul(float2* C, const float2* A, const float2* B) {
    for (int i = 0; i < 4; i++)
        for (int j = 0; j < 4; j++) {
            float2 s = make_float2(0.f, 0.f);
            for (int k = 0; k < 4; k++) s = cfmac(A[i * 4 + k], B[k * 4 + j], s);
            C[i * 4 + j] = s;
        }
}
__device__ void make_u1(const float* th, int layer, int v, float anc, float2* U) {
    float ax = th[3 * v] * 0.5f, ay = th[3 * v + 1] * 0.5f, az = th[3 * v + 2] * 0.5f;
    float cx = cosf(ax), sx = sinf(ax);
    float cy = cosf(ay), sy = sinf(ay);
    float cz = cosf(az), sz = sinf(az);
    float2 m00 = make_float2( cy * cx,  sy * sx);
    float2 m01 = make_float2(-sy * cx, -cy * sx);
    float2 m10 = make_float2( sy * cx, -cy * sx);
    float2 m11 = make_float2( cy * cx, -sy * sx);
    float2 e0 = make_float2(cz, -sz), e1 = make_float2(cz, sz);
    U[0] = cmulc(e0, m00); U[1] = cmulc(e0, m01);
    U[2] = cmulc(e1, m10); U[3] = cmulc(e1, m11);
    if (layer == 0 && v >= 14) {   // absorb initial RY(ancilla_rot): U' = U @ RYa
        float ca = cosf(anc * 0.5f), sa = sinf(anc * 0.5f);
        for (int i = 0; i < 2; i++) {
            float2 u0 = U[i * 2], u1v = U[i * 2 + 1];
            U[i * 2]     = make_float2( u0.x * ca + u1v.x * sa,  u0.y * ca + u1v.y * sa);
            U[i * 2 + 1] = make_float2(-u0.x * sa + u1v.x * ca, -u0.y * sa + u1v.y * ca);
        }
    }
}

__global__ void prep_gates(const float* __restrict__ theta, const float* __restrict__ anc_rot) {
    int id = threadIdx.x;
    if (id >= NLAYERS * NPAIR) return;
    int l = id / NPAIR, w = id % NPAIR;
    const float* th = theta + l * PPL;
    float anc = (anc_rot != nullptr) ? anc_rot[0] : 0.3f;

    float a2 = th[48 + 3 * w] * 0.5f, b2 = th[48 + 3 * w + 1] * 0.5f, c2 = th[48 + 3 * w + 2] * 0.5f;
    float cX = cosf(a2), sX = sinf(a2);
    float cY = cosf(b2), sY = sinf(b2);
    float cZ = cosf(c2), sZ = sinf(c2);

    float2 XX[16], YY[16], ZZ[16], T[16], M[16], K[16], G[16];
    for (int i = 0; i < 16; i++) { XX[i] = YY[i] = ZZ[i] = make_float2(0.f, 0.f); }
    for (int i = 0; i < 4; i++) { XX[i * 4 + i] = make_float2(cX, 0.f); YY[i * 4 + i] = make_float2(cY, 0.f); }
    XX[3] = XX[6] = XX[9] = XX[12] = make_float2(0.f, -sX);
    YY[3]  = make_float2(0.f,  sY); YY[6]  = make_float2(0.f, -sY);
    YY[9]  = make_float2(0.f, -sY); YY[12] = make_float2(0.f,  sY);
    ZZ[0] = ZZ[15] = make_float2(cZ, -sZ);
    ZZ[5] = ZZ[10] = make_float2(cZ,  sZ);

    mat4mul(T, YY, XX);
    mat4mul(M, ZZ, T);

    float2 L[4], R[4];
    if (w == 0) {
        make_u1(th, l, 0, anc, L);
    } else {
        L[0] = make_float2(1.f, 0.f); L[1] = make_float2(0.f, 0.f);
        L[2] = make_float2(0.f, 0.f); L[3] = make_float2(1.f, 0.f);
    }
    make_u1(th, l, w + 1, anc, R);

    for (int a = 0; a < 2; a++)
        for (int b = 0; b < 2; b++)
            for (int c = 0; c < 2; c++)
                for (int d = 0; d < 2; d++)
                    K[(2 * a + b) * 4 + (2 * c + d)] = cmulc(L[a * 2 + c], R[b * 2 + d]);

    mat4mul(G, M, K);
    for (int i = 0; i < 16; i++) {
        g_gates2[l][w][i]      = pack2(G[i].x,  G[i].x);
        g_gates2[l][w][16 + i] = pack2(G[i].y, -G[i].y);
    }
}

// ---------- packed 4x4 complex gate on register bits (B+1,B) ----------
// gs: smem, gs[0..15] = (re,re), gs[16..31] = (im,-im)
// r = d + swap(c): d = sum (gx,gx)*(vx,vy), c = sum (gy,-gy)*(vx,vy)
template <int NB, int B>
__device__ __forceinline__ void apply_pair2(u64* a, const u64* gs) {
    const int s = 1 << B;
#pragma unroll
    for (int hi = 0; hi < (1 << (NB - B - 2)); hi++) {
#pragma unroll
        for (int lo = 0; lo < s; lo++) {
            int i0 = (hi << (B + 2)) | lo;
            u64 v0 = a[i0], v1 = a[i0 + s], v2 = a[i0 + 2 * s], v3 = a[i0 + 3 * s];
#pragma unroll
            for (int r = 0; r < 4; r++) {
                u64 d = fmul2(gs[4 * r], v0);
                d = ffma2(gs[4 * r + 1], v1, d);
                d = ffma2(gs[4 * r + 2], v2, d);
                d = ffma2(gs[4 * r + 3], v3, d);
                u64 c = fmul2(gs[16 + 4 * r], v0);
                c = ffma2(gs[16 + 4 * r + 1], v1, c);
                c = ffma2(gs[16 + 4 * r + 2], v2, c);
                c = ffma2(gs[16 + 4 * r + 3], v3, c);
                a[i0 + r * s] = fadd2(d, swap2(c));
            }
        }
    }
}

// Pairs (0,1),(1,2),(2,3),(3,4) — state bits 15..11. In place on g_state.
__global__ void __launch_bounds__(256, 2) pass_hi(const float* __restrict__ xr, const float* __restrict__ xi,
                                                  int layer, int first) {
    __shared__ u64 sg[4 * 32];
    if (threadIdx.x < 128) sg[threadIdx.x] = g_gates2[layer][threadIdx.x >> 5][threadIdx.x & 31];
    __syncthreads();

    unsigned tid  = blockIdx.x * 256u + threadIdx.x;
    unsigned b    = tid >> 11;
    unsigned rest = tid & 2047u;
    unsigned base = (b << 16) | rest;

    u64 a[32];
    if (first) {
#pragma unroll
        for (int h = 0; h < 32; h++) {
            unsigned off = (base + ((unsigned)h << 11)) & MASKN;
            a[h] = pack2(xr[off], xi[off]);
        }
    } else {
#pragma unroll
        for (int h = 0; h < 32; h++) a[h] = g_state[(base + ((unsigned)h << 11)) & MASKN];
    }

    apply_pair2<5, 3>(a, sg);        // (0,1)
    apply_pair2<5, 2>(a, sg + 32);   // (1,2)
    apply_pair2<5, 1>(a, sg + 64);   // (2,3)
    apply_pair2<5, 0>(a, sg + 96);   // (3,4)

#pragma unroll
    for (int h = 0; h < 32; h++) g_state[(base + ((unsigned)h << 11)) & MASKN] = a[h];
}

// Pairs (4,5)..(14,15) — state bits 11..0. 4096-amp tile, 32 KB static smem.
// dst = g_state (mid layers) or d_out (last layer, when out_size == 2*NSTATE).
__global__ void __launch_bounds__(128, 4) pass_lo(u64* __restrict__ dst, int layer) {
    __shared__ u64 tile[4096];
    __shared__ u64 sgl[11 * 32];
    for (int i = threadIdx.x; i < 11 * 32; i += 128)
        sgl[i] = g_gates2[layer][4 + (i >> 5)][i & 31];

    unsigned b    = blockIdx.x >> 4;
    unsigned hi4  = blockIdx.x & 15u;
    unsigned base = (b << 16) | (hi4 << 12);
    unsigned t    = threadIdx.x;

    u64 a[32];

    // stage A: regs = tile bits 11..7, thread = bits 6..0 (coalesced)
#pragma unroll
    for (int r = 0; r < 32; r++) a[r] = g_state[(base + ((unsigned)r << 7) + t) & MASKN];
    __syncthreads();
    apply_pair2<5, 3>(a, sgl);                  // (4,5)
    apply_pair2<5, 2>(a, sgl + 32);             // (5,6)
    apply_pair2<5, 1>(a, sgl + 64);             // (6,7)
    apply_pair2<5, 0>(a, sgl + 96);             // (7,8)
#pragma unroll
    for (int r = 0; r < 32; r++) { unsigned i = ((unsigned)r << 7) | t; tile[SW(i)] = a[r]; }
    __syncthreads();

    // stage B: regs = bits 7..3, thread = bits 11..8 | 2..0
    unsigned thi = t >> 3, tlo = t & 7u;
#pragma unroll
    for (int r = 0; r < 32; r++) { unsigned i = (thi << 8) | ((unsigned)r << 3) | tlo; a[r] = tile[SW(i)]; }
    apply_pair2<5, 3>(a, sgl + 128);            // (8,9)
    apply_pair2<5, 2>(a, sgl + 160);            // (9,10)
    apply_pair2<5, 1>(a, sgl + 192);            // (10,11)
    apply_pair2<5, 0>(a, sgl + 224);            // (11,12)
#pragma unroll
    for (int r = 0; r < 32; r++) { unsigned i = (thi << 8) | ((unsigned)r << 3) | tlo; tile[SW(i)] = a[r]; }
    __syncthreads();

    // stage C: regs = bits 4..0, thread = bits 11..5
#pragma unroll
    for (int r = 0; r < 32; r++) { unsigned i = (t << 5) | (unsigned)r; a[r] = tile[SW(i)]; }
    apply_pair2<5, 2>(a, sgl + 256);            // (12,13)
    apply_pair2<5, 1>(a, sgl + 288);            // (13,14)
    apply_pair2<5, 0>(a, sgl + 320);            // (14,15)
#pragma unroll
    for (int r = 0; r < 32; r++) { unsigned i = (t << 5) | (unsigned)r; tile[SW(i)] = a[r]; }
    __syncthreads();

    // coalesced writeout
#pragma unroll
    for (int r = 0; r < 32; r++) { unsigned i = ((unsigned)r << 7) | t; dst[(base + i) & MASKN] = tile[SW(i)]; }
}

// Fallback epilogue (only used if out_size != 2*NSTATE): bounded stores only.
__global__ void writeout(float* __restrict__ out, int out_size, int mode) {
    int i = blockIdx.x * 256 + threadIdx.x;
    if (i >= out_size) return;
    float2 v = ((const float2*)g_state)[(mode ? (i >> 1) : i) & MASKN];
    out[i] = mode ? ((i & 1) ? v.y : v.x) : v.x;
}

__global__ void zero_out(float* out, int out_size) {
    int i = blockIdx.x * 256 + threadIdx.x;
    if (i < out_size) out[i] = 0.f;
}

extern "C" void kernel_launch(void* const* d_in, const int* in_sizes, int n_in,
                              void* d_out, int out_size) {
    // Size-scan binding (element counts or byte counts). Never index past n_in.
    const float* big[2] = {nullptr, nullptr};
    const float* theta  = nullptr;
    const float* anc    = nullptr;
    int nbig = 0;
    int first_big_idx = -1;
    for (int i = 0; i < n_in; i++) {
        long long s = in_sizes[i];
        if (s == (long long)NSTATE || s == (long long)NSTATE * 4) {
            if (nbig < 2) { big[nbig++] = (const float*)d_in[i]; if (first_big_idx < 0) first_big_idx = i; }
        } else if (s == NLAYERS * PPL || s == NLAYERS * PPL * 4) {
            theta = (const float*)d_in[i];
        } else if (s >= 1 && s <= 4) {
            if (!anc) anc = (const float*)d_in[i];
        }
    }

    float* outf = (float*)d_out;
    int nblk_out = (out_size + 255) / 256;
    if (nblk_out <= 0) nblk_out = 1;

    if (nbig < 2 || !theta) {
        zero_out<<<nblk_out, 256>>>(outf, out_size);
        return;
    }

    const float* xr = big[0];
    const float* xi = big[1];
    if (first_big_idx > 0) { xr = big[1]; xi = big[0]; }

    // d_out holds NSTATE interleaved complex64 (verified by round-7 pass).
    bool direct = (out_size == 2 * NSTATE);

    u64* state_sym = nullptr;  // written via kernels only; pointer for dst arg
    // Use a small kernel-visible alias: g_state is a device symbol; pass_lo
    // writes through the dst pointer, so get its address without allocations.
    cudaGetSymbolAddress((void**)&state_sym, g_state);

    prep_gates<<<1, 64>>>(theta, anc);
    for (int l = 0; l < NLAYERS; l++) {
        pass_hi<<<(BATCH * 2048) / 256, 256>>>(xr, xi, l, l == 0 ? 1 : 0);
        u64* dst = (l == NLAYERS - 1 && direct) ? (u64*)d_out : state_sym;
        pass_lo<<<BATCH * 16, 128>>>(dst, l);
    }
    if (!direct) {
        int mode = (out_size >= 2 * NSTATE) ? 1 : 0;
        writeout<<<nblk_out, 256>>>(outf, out_size, mode);
    }
}

// round 10
// speedup vs baseline: 1.3304x; 1.3304x over previous
#include <cuda_runtime.h>

#define NQ      16
#define DSTATE  (1 << NQ)      // 65536
#define BATCH   64
#define NLAYERS 4
#define PPL     93
#define NPAIR   15
#define NSTATE  (BATCH * DSTATE)
#define MASKN   (NSTATE - 1)

// XOR swizzle on u64 tile index: conflict-free for all stage access patterns
#define SW(i) (((i) ^ (((i) >> 5) & 31)) & 4095)

typedef unsigned long long u64;

// scratch state (32 MB) + dual-packed fused gate matrices
// gate layout per gate: [row*8 + k] = (re,re) of G[row][k], [row*8 + 4 + k] = (im,im)
__device__ u64 g_state[NSTATE];
__device__ u64 g_gates2[NLAYERS][NPAIR][32];

// ---------- packed f32x2 helpers ----------
__device__ __forceinline__ u64 pack2(float x, float y) {
    u64 r; asm("mov.b64 %0, {%1, %2};" : "=l"(r) : "f"(x), "f"(y)); return r;
}
__device__ __forceinline__ u64 ffma2(u64 a, u64 b, u64 c) {
    u64 r; asm("fma.rn.f32x2 %0, %1, %2, %3;" : "=l"(r) : "l"(a), "l"(b), "l"(c)); return r;
}
__device__ __forceinline__ u64 fmul2(u64 a, u64 b) {
    u64 r; asm("mul.rn.f32x2 %0, %1, %2;" : "=l"(r) : "l"(a), "l"(b)); return r;
}
// v = (vx, vy) -> (-vy, vx)
__device__ __forceinline__ u64 negswap(u64 v) {
    u64 r;
    asm("{ .reg .b32 lo, hi; mov.b64 {lo, hi}, %1; neg.f32 hi, hi; mov.b64 %0, {hi, lo}; }"
        : "=l"(r) : "l"(v));
    return r;
}

// ---------- gate preparation (scalar complex, trivial cost) ----------
__device__ __forceinline__ float2 cmulc(float2 a, float2 b) {
    return make_float2(a.x * b.x - a.y * b.y, a.x * b.y + a.y * b.x);
}
__device__ __forceinline__ float2 cfmac(float2 a, float2 b, float2 c) {
    c.x = fmaf(a.x, b.x, fmaf(-a.y, b.y, c.x));
    c.y = fmaf(a.x, b.y, fmaf(a.y, b.x, c.y));
    return c;
}
__device__ void mat4mul(float2* C, const float2* A, const float2* B) {
    for (int i = 0; i < 4; i++)
        for (int j = 0; j < 4; j++) {
            float2 s = make_float2(0.f, 0.f);
            for (int k = 0; k < 4; k++) s = cfmac(A[i * 4 + k], B[k * 4 + j], s);
            C[i * 4 + j] = s;
        }
}
__device__ void make_u1(const float* th, int layer, int v, float anc, float2* U) {
    float ax = th[3 * v] * 0.5f, ay = th[3 * v + 1] * 0.5f, az = th[3 * v + 2] * 0.5f;
    float cx = cosf(ax), sx = sinf(ax);
    float cy = cosf(ay), sy = sinf(ay);
    float cz = cosf(az), sz = sinf(az);
    float2 m00 = make_float2( cy * cx,  sy * sx);
    float2 m01 = make_float2(-sy * cx, -cy * sx);
    float2 m10 = make_float2( sy * cx, -cy * sx);
    float2 m11 = make_float2( cy * cx, -sy * sx);
    float2 e0 = make_float2(cz, -sz), e1 = make_float2(cz, sz);
    U[0] = cmulc(e0, m00); U[1] = cmulc(e0, m01);
    U[2] = cmulc(e1, m10); U[3] = cmulc(e1, m11);
    if (layer == 0 && v >= 14) {   // absorb initial RY(ancilla_rot): U' = U @ RYa
        float ca = cosf(anc * 0.5f), sa = sinf(anc * 0.5f);
        for (int i = 0; i < 2; i++) {
            float2 u0 = U[i * 2], u1v = U[i * 2 + 1];
            U[i * 2]     = make_float2( u0.x * ca + u1v.x * sa,  u0.y * ca + u1v.y * sa);
            U[i * 2 + 1] = make_float2(-u0.x * sa + u1v.x * ca, -u0.y * sa + u1v.y * ca);
        }
    }
}

__global__ void prep_gates(const float* __restrict__ theta, const float* __restrict__ anc_rot) {
    int id = threadIdx.x;
    if (id >= NLAYERS * NPAIR) return;
    int l = id / NPAIR, w = id % NPAIR;
    const float* th = theta + l * PPL;
    float anc = (anc_rot != nullptr) ? anc_rot[0] : 0.3f;

    float a2 = th[48 + 3 * w] * 0.5f, b2 = th[48 + 3 * w + 1] * 0.5f, c2 = th[48 + 3 * w + 2] * 0.5f;
    float cX = cosf(a2), sX = sinf(a2);
    float cY = cosf(b2), sY = sinf(b2);
    float cZ = cosf(c2), sZ = sinf(c2);

    float2 XX[16], YY[16], ZZ[16], T[16], M[16], K[16], G[16];
    for (int i = 0; i < 16; i++) { XX[i] = YY[i] = ZZ[i] = make_float2(0.f, 0.f); }
    for (int i = 0; i < 4; i++) { XX[i * 4 + i] = make_float2(cX, 0.f); YY[i * 4 + i] = make_float2(cY, 0.f); }
    XX[3] = XX[6] = XX[9] = XX[12] = make_float2(0.f, -sX);
    YY[3]  = make_float2(0.f,  sY); YY[6]  = make_float2(0.f, -sY);
    YY[9]  = make_float2(0.f, -sY); YY[12] = make_float2(0.f,  sY);
    ZZ[0] = ZZ[15] = make_float2(cZ, -sZ);
    ZZ[5] = ZZ[10] = make_float2(cZ,  sZ);

    mat4mul(T, YY, XX);
    mat4mul(M, ZZ, T);

    float2 L[4], R[4];
    if (w == 0) {
        make_u1(th, l, 0, anc, L);
    } else {
        L[0] = make_float2(1.f, 0.f); L[1] = make_float2(0.f, 0.f);
        L[2] = make_float2(0.f, 0.f); L[3] = make_float2(1.f, 0.f);
    }
    make_u1(th, l, w + 1, anc, R);

    for (int a = 0; a < 2; a++)
        for (int b = 0; b < 2; b++)
            for (int c = 0; c < 2; c++)
                for (int d = 0; d < 2; d++)
                    K[(2 * a + b) * 4 + (2 * c + d)] = cmulc(L[a * 2 + c], R[b * 2 + d]);

    mat4mul(G, M, K);
    for (int r = 0; r < 4; r++)
        for (int k = 0; k < 4; k++) {
            float2 Gv = G[r * 4 + k];
            g_gates2[l][w][r * 8 + k]     = pack2(Gv.x, Gv.x);
            g_gates2[l][w][r * 8 + 4 + k] = pack2(Gv.y, Gv.y);
        }
}

// ---------- packed 4x4 complex gate on register bits (B+1,B) ----------
// Gates cached in registers (one 32-LDS burst per call). Per 4-amp group:
// w_k = (-v_k.y, v_k.x); row r: acc = sum_k (gx,gx)*v_k + (gy,gy)*w_k.
template <int NB, int B>
__device__ __forceinline__ void apply_pair2(u64* a, const u64* gs) {
    u64 g[32];
#pragma unroll
    for (int i = 0; i < 32; i++) g[i] = gs[i];
    const int s = 1 << B;
#pragma unroll
    for (int hi = 0; hi < (1 << (NB - B - 2)); hi++) {
#pragma unroll
        for (int lo = 0; lo < s; lo++) {
            int i0 = (hi << (B + 2)) | lo;
            u64 v0 = a[i0], v1 = a[i0 + s], v2 = a[i0 + 2 * s], v3 = a[i0 + 3 * s];
            u64 w0 = negswap(v0), w1 = negswap(v1), w2 = negswap(v2), w3 = negswap(v3);
#pragma unroll
            for (int r = 0; r < 4; r++) {
                u64 acc = fmul2(g[8 * r], v0);
                acc = ffma2(g[8 * r + 1], v1, acc);
                acc = ffma2(g[8 * r + 2], v2, acc);
                acc = ffma2(g[8 * r + 3], v3, acc);
                acc = ffma2(g[8 * r + 4], w0, acc);
                acc = ffma2(g[8 * r + 5], w1, acc);
                acc = ffma2(g[8 * r + 6], w2, acc);
                acc = ffma2(g[8 * r + 7], w3, acc);
                a[i0 + r * s] = acc;
            }
        }
    }
}

// Pairs (0,1),(1,2),(2,3),(3,4) — state bits 15..11. In place on g_state.
__global__ void __launch_bounds__(128, 3) pass_hi(const float* __restrict__ xr, const float* __restrict__ xi,
                                                  int layer, int first) {
    __shared__ u64 sg[4 * 32];
    if (threadIdx.x < 128) sg[threadIdx.x] = g_gates2[layer][threadIdx.x >> 5][threadIdx.x & 31];
    __syncthreads();

    unsigned tid  = blockIdx.x * 128u + threadIdx.x;   // 131072 threads
    unsigned b    = tid >> 11;
    unsigned rest = tid & 2047u;
    unsigned base = (b << 16) | rest;

    u64 a[32];
    if (first) {
#pragma unroll
        for (int h = 0; h < 32; h++) {
            unsigned off = (base + ((unsigned)h << 11)) & MASKN;
            a[h] = pack2(xr[off], xi[off]);
        }
    } else {
#pragma unroll
        for (int h = 0; h < 32; h++) a[h] = g_state[(base + ((unsigned)h << 11)) & MASKN];
    }

    apply_pair2<5, 3>(a, sg);        // (0,1)
    apply_pair2<5, 2>(a, sg + 32);   // (1,2)
    apply_pair2<5, 1>(a, sg + 64);   // (2,3)
    apply_pair2<5, 0>(a, sg + 96);   // (3,4)

#pragma unroll
    for (int h = 0; h < 32; h++) g_state[(base + ((unsigned)h << 11)) & MASKN] = a[h];
}

// Pairs (4,5)..(14,15) — state bits 11..0. 4096-amp tile, 32 KB static smem.
// dst = g_state (mid layers) or d_out (last layer, out_size == 2*NSTATE).
__global__ void __launch_bounds__(128, 3) pass_lo(u64* __restrict__ dst, int layer) {
    __shared__ u64 tile[4096];
    __shared__ u64 sgl[11 * 32];
    for (int i = threadIdx.x; i < 11 * 32; i += 128)
        sgl[i] = g_gates2[layer][4 + (i >> 5)][i & 31];

    unsigned b    = blockIdx.x >> 4;
    unsigned hi4  = blockIdx.x & 15u;
    unsigned base = (b << 16) | (hi4 << 12);
    unsigned t    = threadIdx.x;

    u64 a[32];

    // stage A: regs = tile bits 11..7, thread = bits 6..0 (coalesced)
#pragma unroll
    for (int r = 0; r < 32; r++) a[r] = g_state[(base + ((unsigned)r << 7) + t) & MASKN];
    __syncthreads();
    apply_pair2<5, 3>(a, sgl);                  // (4,5)
    apply_pair2<5, 2>(a, sgl + 32);             // (5,6)
    apply_pair2<5, 1>(a, sgl + 64);             // (6,7)
    apply_pair2<5, 0>(a, sgl + 96);             // (7,8)
#pragma unroll
    for (int r = 0; r < 32; r++) { unsigned i = ((unsigned)r << 7) | t; tile[SW(i)] = a[r]; }
    __syncthreads();

    // stage B: regs = bits 7..3, thread = bits 11..8 | 2..0
    unsigned thi = t >> 3, tlo = t & 7u;
#pragma unroll
    for (int r = 0; r < 32; r++) { unsigned i = (thi << 8) | ((unsigned)r << 3) | tlo; a[r] = tile[SW(i)]; }
    apply_pair2<5, 3>(a, sgl + 128);            // (8,9)
    apply_pair2<5, 2>(a, sgl + 160);            // (9,10)
    apply_pair2<5, 1>(a, sgl + 192);            // (10,11)
    apply_pair2<5, 0>(a, sgl + 224);            // (11,12)
#pragma unroll
    for (int r = 0; r < 32; r++) { unsigned i = (thi << 8) | ((unsigned)r << 3) | tlo; tile[SW(i)] = a[r]; }
    __syncthreads();

    // stage C: regs = bits 4..0, thread = bits 11..5
#pragma unroll
    for (int r = 0; r < 32; r++) { unsigned i = (t << 5) | (unsigned)r; a[r] = tile[SW(i)]; }
    apply_pair2<5, 2>(a, sgl + 256);            // (12,13)
    apply_pair2<5, 1>(a, sgl + 288);            // (13,14)
    apply_pair2<5, 0>(a, sgl + 320);            // (14,15)
#pragma unroll
    for (int r = 0; r < 32; r++) { unsigned i = (t << 5) | (unsigned)r; tile[SW(i)] = a[r]; }
    __syncthreads();

    // coalesced writeout
#pragma unroll
    for (int r = 0; r < 32; r++) { unsigned i = ((unsigned)r << 7) | t; dst[(base + i) & MASKN] = tile[SW(i)]; }
}

// Fallback epilogue (only if out_size != 2*NSTATE): bounded stores only.
__global__ void writeout(float* __restrict__ out, int out_size, int mode) {
    int i = blockIdx.x * 256 + threadIdx.x;
    if (i >= out_size) return;
    float2 v = ((const float2*)g_state)[(mode ? (i >> 1) : i) & MASKN];
    out[i] = mode ? ((i & 1) ? v.y : v.x) : v.x;
}

__global__ void zero_out(float* out, int out_size) {
    int i = blockIdx.x * 256 + threadIdx.x;
    if (i < out_size) out[i] = 0.f;
}

extern "C" void kernel_launch(void* const* d_in, const int* in_sizes, int n_in,
                              void* d_out, int out_size) {
    // Size-scan binding (element counts or byte counts). Never index past n_in.
    const float* big[2] = {nullptr, nullptr};
    const float* theta  = nullptr;
    const float* anc    = nullptr;
    int nbig = 0;
    int first_big_idx = -1;
    for (int i = 0; i < n_in; i++) {
        long long s = in_sizes[i];
        if (s == (long long)NSTATE || s == (long long)NSTATE * 4) {
            if (nbig < 2) { big[nbig++] = (const float*)d_in[i]; if (first_big_idx < 0) first_big_idx = i; }
        } else if (s == NLAYERS * PPL || s == NLAYERS * PPL * 4) {
            theta = (const float*)d_in[i];
        } else if (s >= 1 && s <= 4) {
            if (!anc) anc = (const float*)d_in[i];
        }
    }

    float* outf = (float*)d_out;
    int nblk_out = (out_size + 255) / 256;
    if (nblk_out <= 0) nblk_out = 1;

    if (nbig < 2 || !theta) {
        zero_out<<<nblk_out, 256>>>(outf, out_size);
        return;
    }

    const float* xr = big[0];
    const float* xi = big[1];
    if (first_big_idx > 0) { xr = big[1]; xi = big[0]; }

    // d_out holds NSTATE interleaved complex64 (verified by round-7/8 passes).
    bool direct = (out_size == 2 * NSTATE);

    u64* state_sym = nullptr;
    cudaGetSymbolAddress((void**)&state_sym, g_state);

    prep_gates<<<1, 64>>>(theta, anc);
    for (int l = 0; l < NLAYERS; l++) {
        pass_hi<<<(BATCH * 2048) / 128, 128>>>(xr, xi, l, l == 0 ? 1 : 0);
        u64* dst = (l == NLAYERS - 1 && direct) ? (u64*)d_out : state_sym;
        pass_lo<<<BATCH * 16, 128>>>(dst, l);
    }
    if (!direct) {
        int mode = (out_size >= 2 * NSTATE) ? 1 : 0;
        writeout<<<nblk_out, 256>>>(outf, out_size, mode);
    }
}